// round 14
// baseline (speedup 1.0000x reference)
#include <cuda_runtime.h>
#include <cstdint>

#define D_MODEL 1024
#define SEQLEN  2048
#define BATCH   4
#define NHEADS  16
#define HDIM    64
#define MROWS   (BATCH * SEQLEN)   /* 8192 */
#define INV_TAU (1.0f / 0.07f)

// ---------------- scratch (__device__ globals; no allocs allowed) ----------
__device__ uint32_t g_qh[MROWS * D_MODEL / 2], g_ql[MROWS * D_MODEL / 2];
__device__ uint32_t g_kh[MROWS * D_MODEL / 2], g_kl[MROWS * D_MODEL / 2];
__device__ uint32_t g_vh[MROWS * D_MODEL / 2], g_vl[MROWS * D_MODEL / 2];
__device__ uint32_t g_ah[MROWS * D_MODEL / 2], g_al[MROWS * D_MODEL / 2];
__device__ uint32_t g_wqh[D_MODEL * D_MODEL / 2], g_wql[D_MODEL * D_MODEL / 2];
__device__ uint32_t g_wkh[D_MODEL * D_MODEL / 2], g_wkl[D_MODEL * D_MODEL / 2];
__device__ uint32_t g_wvh[D_MODEL * D_MODEL / 2], g_wvl[D_MODEL * D_MODEL / 2];
__device__ uint32_t g_woh[D_MODEL * D_MODEL / 2], g_wol[D_MODEL * D_MODEL / 2];
__device__ uint32_t g_qh2[MROWS * D_MODEL / 2], g_ql2[MROWS * D_MODEL / 2];
__device__ uint32_t g_kh2[MROWS * D_MODEL / 2], g_kl2[MROWS * D_MODEL / 2];
__device__ uint32_t g_vt2[MROWS * D_MODEL];

// ---------------- helpers --------------------------------------------------
__device__ __forceinline__ uint32_t f2tf32(float f) {
    uint32_t r; asm("cvt.rna.tf32.f32 %0, %1;" : "=r"(r) : "f"(f)); return r;
}
__device__ __forceinline__ void mma8(float* c, const uint32_t* a, const uint32_t* b) {
    asm volatile("mma.sync.aligned.m16n8k8.row.col.f32.tf32.tf32.f32 "
        "{%0,%1,%2,%3},{%4,%5,%6,%7},{%8,%9},{%0,%1,%2,%3};"
        : "+f"(c[0]), "+f"(c[1]), "+f"(c[2]), "+f"(c[3])
        : "r"(a[0]), "r"(a[1]), "r"(a[2]), "r"(a[3]), "r"(b[0]), "r"(b[1]));
}
__device__ __forceinline__ void mma16(float* c, const uint32_t* a, const uint32_t* b) {
    asm volatile("mma.sync.aligned.m16n8k16.row.col.f32.bf16.bf16.f32 "
        "{%0,%1,%2,%3},{%4,%5,%6,%7},{%8,%9},{%0,%1,%2,%3};"
        : "+f"(c[0]), "+f"(c[1]), "+f"(c[2]), "+f"(c[3])
        : "r"(a[0]), "r"(a[1]), "r"(a[2]), "r"(a[3]), "r"(b[0]), "r"(b[1]));
}
__device__ __forceinline__ uint32_t hipack(float e, float o) {
    return __byte_perm(__float_as_uint(e), __float_as_uint(o), 0x7632);
}
__device__ __forceinline__ uint32_t lopack(float e, float o) {
    uint32_t r; asm("cvt.rn.bf16x2.f32 %0, %1, %2;" : "=r"(r) : "f"(o), "f"(e));
    return r;
}
__device__ __forceinline__ float truncbf(float x) {
    return __uint_as_float(__float_as_uint(x) & 0xffff0000u);
}
__device__ __forceinline__ void split2(float e, float o, uint32_t& h, uint32_t& l) {
    h = hipack(e, o);
    l = lopack(e - truncbf(e), o - truncbf(o));
}
__device__ __forceinline__ void cpa16(uint32_t sdst, const void* gsrc) {
    asm volatile("cp.async.cg.shared.global [%0], [%1], 16;" :: "r"(sdst), "l"(gsrc));
}
#define CPA_COMMIT() asm volatile("cp.async.commit_group;" ::: "memory")
#define CPA_WAIT1()  asm volatile("cp.async.wait_group 1;" ::: "memory")
#define CPA_WAIT0()  asm volatile("cp.async.wait_group 0;" ::: "memory")

// ---------------------------------------------------------------------------
__global__ __launch_bounds__(256) void splits3(
    const float* __restrict__ Xq, const float* __restrict__ Xk,
    const float* __restrict__ Xv,
    uint32_t* __restrict__ Hq, uint32_t* __restrict__ Lq,
    uint32_t* __restrict__ Hk, uint32_t* __restrict__ Lk,
    uint32_t* __restrict__ Hv, uint32_t* __restrict__ Lv, int n4)
{
    int i = blockIdx.x * blockDim.x + threadIdx.x;
    if (i >= n4) return;
    float4 a = ((const float4*)Xq)[i];
    float4 b = ((const float4*)Xk)[i];
    float4 c = ((const float4*)Xv)[i];
    uint32_t h0, l0, h1, l1;
    split2(a.x, a.y, h0, l0); split2(a.z, a.w, h1, l1);
    ((uint2*)Hq)[i] = make_uint2(h0, h1); ((uint2*)Lq)[i] = make_uint2(l0, l1);
    split2(b.x, b.y, h0, l0); split2(b.z, b.w, h1, l1);
    ((uint2*)Hk)[i] = make_uint2(h0, h1); ((uint2*)Lk)[i] = make_uint2(l0, l1);
    split2(c.x, c.y, h0, l0); split2(c.z, c.w, h1, l1);
    ((uint2*)Hv)[i] = make_uint2(h0, h1); ((uint2*)Lv)[i] = make_uint2(l0, l1);
}

__global__ __launch_bounds__(256) void wsplit4(
    const float* __restrict__ W0, const float* __restrict__ W1,
    const float* __restrict__ W2, const float* __restrict__ W3,
    uint32_t* __restrict__ H0, uint32_t* __restrict__ L0,
    uint32_t* __restrict__ H1, uint32_t* __restrict__ L1,
    uint32_t* __restrict__ H2, uint32_t* __restrict__ L2,
    uint32_t* __restrict__ H3, uint32_t* __restrict__ L3, int n4)
{
    int i = blockIdx.x * blockDim.x + threadIdx.x;
    if (i >= n4) return;
    int wsel = blockIdx.y;
    const float* X = (wsel == 0) ? W0 : (wsel == 1) ? W1 : (wsel == 2) ? W2 : W3;
    uint32_t* Hi   = (wsel == 0) ? H0 : (wsel == 1) ? H1 : (wsel == 2) ? H2 : H3;
    uint32_t* Lo   = (wsel == 0) ? L0 : (wsel == 1) ? L1 : (wsel == 2) ? L2 : L3;
    float4 v = ((const float4*)X)[i];
    uint32_t h0, l0, h1, l1;
    split2(v.x, v.y, h0, l0);
    split2(v.z, v.w, h1, l1);
    ((uint2*)Hi)[i] = make_uint2(h0, h1);
    ((uint2*)Lo)[i] = make_uint2(l0, l1);
}

// ---------------------------------------------------------------------------
// Split-bf16 GEMM (3-pass), cp.async 3-stage pipeline (prefetch distance 2).
// Dynamic smem: 4 arrays x 3 stages x 1536 u32 = 73728 bytes.
// OUT 0: fp32. OUT 1: tf32 per-head. OUT 2/3: fused l2norm(+tau)+split.
// ---------------------------------------------------------------------------
#define GST (128 * 12)          /* 1536 u32 per stage per array */
#define GSM_BYTES (4 * 3 * GST * 4)

template<int OUT>
__global__ __launch_bounds__(256) void gemm_ps(
    const uint32_t* __restrict__ Ahi, const uint32_t* __restrict__ Alo,
    const uint32_t* __restrict__ Bhi, const uint32_t* __restrict__ Blo,
    const float* __restrict__ bias, void* __restrict__ Cout,
    void* __restrict__ Cout2)
{
    extern __shared__ __align__(16) uint32_t dsm[];
    uint32_t* AHb = dsm;
    uint32_t* ALb = dsm + 3 * GST;
    uint32_t* BHb = dsm + 6 * GST;
    uint32_t* BLb = dsm + 9 * GST;

    const int N = D_MODEL;
    const int t    = threadIdx.x;
    const int lane = t & 31, wid = t >> 5;
    const int wm   = wid >> 2, wn = wid & 3;
    const int brow = blockIdx.y * 128, bcol = blockIdx.x * 128;
    const int lr   = t >> 1;
    const int lkp  = (t & 1) * 4;
    const int sbi  = lr * 12 + lkp;

    const uint32_t* gAh = Ahi + (size_t)(brow + lr) * 512 + lkp;
    const uint32_t* gAl = Alo + (size_t)(brow + lr) * 512 + lkp;
    const uint32_t* gBh = Bhi + (size_t)(bcol + lr) * 512 + lkp;
    const uint32_t* gBl = Blo + (size_t)(bcol + lr) * 512 + lkp;

    uint32_t sAH[3], sAL[3], sBH[3], sBL[3];
#pragma unroll
    for (int s = 0; s < 3; s++) {
        sAH[s] = (uint32_t)__cvta_generic_to_shared(&AHb[s * GST + sbi]);
        sAL[s] = (uint32_t)__cvta_generic_to_shared(&ALb[s * GST + sbi]);
        sBH[s] = (uint32_t)__cvta_generic_to_shared(&BHb[s * GST + sbi]);
        sBL[s] = (uint32_t)__cvta_generic_to_shared(&BLb[s * GST + sbi]);
    }

    float acc[4][4][4];
#pragma unroll
    for (int mt = 0; mt < 4; mt++)
#pragma unroll
        for (int nt = 0; nt < 4; nt++)
#pragma unroll
            for (int i = 0; i < 4; i++) acc[mt][nt][i] = 0.f;

    // prologue: chunks 0,1 -> stages 0,1 (two groups in flight)
#pragma unroll
    for (int p = 0; p < 2; p++) {
        cpa16(sAH[p], gAh + p * 8); cpa16(sAL[p], gAl + p * 8);
        cpa16(sBH[p], gBh + p * 8); cpa16(sBL[p], gBl + p * 8);
        CPA_COMMIT();
    }

    int s = 0;
    for (int c = 0; c < 64; c++) {
        CPA_WAIT1();
        __syncthreads();
        if (c < 62) {
            int s2 = s + 2; if (s2 >= 3) s2 -= 3;
            cpa16(sAH[s2], gAh + (c + 2) * 8);
            cpa16(sAL[s2], gAl + (c + 2) * 8);
            cpa16(sBH[s2], gBh + (c + 2) * 8);
            cpa16(sBL[s2], gBl + (c + 2) * 8);
            CPA_COMMIT();
        } else {
            CPA_COMMIT();   // keep group count in step for WAIT1 semantics
        }
        {
            const uint32_t* AH = AHb + s * GST;
            const uint32_t* AL = ALb + s * GST;
            const uint32_t* BH = BHb + s * GST;
            const uint32_t* BL = BLb + s * GST;
            const int kk = lane & 3;
            uint32_t ah[4][4], al[4][4], bh[4][2], bl[4][2];
#pragma unroll
            for (int mt = 0; mt < 4; mt++) {
                int r = wm * 64 + mt * 16 + (lane >> 2);
                ah[mt][0] = AH[r * 12 + kk];
                ah[mt][1] = AH[(r + 8) * 12 + kk];
                ah[mt][2] = AH[r * 12 + kk + 4];
                ah[mt][3] = AH[(r + 8) * 12 + kk + 4];
                al[mt][0] = AL[r * 12 + kk];
                al[mt][1] = AL[(r + 8) * 12 + kk];
                al[mt][2] = AL[r * 12 + kk + 4];
                al[mt][3] = AL[(r + 8) * 12 + kk + 4];
            }
#pragma unroll
            for (int nt = 0; nt < 4; nt++) {
                int n = wn * 32 + nt * 8 + (lane >> 2);
                bh[nt][0] = BH[n * 12 + kk];
                bh[nt][1] = BH[n * 12 + kk + 4];
                bl[nt][0] = BL[n * 12 + kk];
                bl[nt][1] = BL[n * 12 + kk + 4];
            }
#pragma unroll
            for (int mt = 0; mt < 4; mt++)
#pragma unroll
                for (int nt = 0; nt < 4; nt++) {
                    mma16(acc[mt][nt], ah[mt], bh[nt]);
                    mma16(acc[mt][nt], ah[mt], bl[nt]);
                    mma16(acc[mt][nt], al[mt], bh[nt]);
                }
        }
        if (++s == 3) s = 0;
    }
    CPA_WAIT0();

    // ---- bias ----
#pragma unroll
    for (int nt = 0; nt < 4; nt++) {
        int gc = bcol + wn * 32 + nt * 8 + (lane & 3) * 2;
        float2 bb = *(const float2*)(bias + gc);
#pragma unroll
        for (int mt = 0; mt < 4; mt++) {
            acc[mt][nt][0] += bb.x; acc[mt][nt][1] += bb.y;
            acc[mt][nt][2] += bb.x; acc[mt][nt][3] += bb.y;
        }
    }

    if (OUT == 0 || OUT == 1) {
#pragma unroll
        for (int mt = 0; mt < 4; mt++)
#pragma unroll
            for (int nt = 0; nt < 4; nt++) {
                int gr = brow + wm * 64 + mt * 16 + (lane >> 2);
                int gc = bcol + wn * 32 + nt * 8 + (lane & 3) * 2;
                if (OUT == 0) {
                    float* C = (float*)Cout;
                    *(float2*)(C + (size_t)gr * N + gc) =
                        make_float2(acc[mt][nt][0], acc[mt][nt][1]);
                    *(float2*)(C + (size_t)(gr + 8) * N + gc) =
                        make_float2(acc[mt][nt][2], acc[mt][nt][3]);
                } else {
                    uint32_t* C = (uint32_t*)Cout;
                    int bidx = gr >> 11, pos = gr & 2047;
                    int h = gc >> 6, d = gc & 63;
                    size_t i0 = ((size_t)(bidx * NHEADS + h) * SEQLEN + pos) * 64 + d;
                    *(uint2*)(C + i0)          = make_uint2(f2tf32(acc[mt][nt][0]), f2tf32(acc[mt][nt][1]));
                    *(uint2*)(C + i0 + 8 * 64) = make_uint2(f2tf32(acc[mt][nt][2]), f2tf32(acc[mt][nt][3]));
                }
            }
    } else {
        // ---- fused l2norm + split epilogue ----
        __syncthreads();
        float* red = (float*)dsm;      // scratch [wm][64][4]
#pragma unroll
        for (int mt = 0; mt < 4; mt++)
#pragma unroll
            for (int half = 0; half < 2; half++) {
                float s2 = 0.f;
#pragma unroll
                for (int nt = 0; nt < 4; nt++) {
                    float v0 = acc[mt][nt][half * 2 + 0];
                    float v1 = acc[mt][nt][half * 2 + 1];
                    s2 += v0 * v0 + v1 * v1;
                }
                s2 += __shfl_xor_sync(0xffffffffu, s2, 1);
                s2 += __shfl_xor_sync(0xffffffffu, s2, 2);
                int rl = mt * 16 + (lane >> 2) + half * 8;
                if ((lane & 3) == 0) red[wm * 256 + rl * 4 + wn] = s2;
            }
        __syncthreads();
        uint32_t* Hi = (uint32_t*)Cout;
        uint32_t* Lo = (uint32_t*)Cout2;
#pragma unroll
        for (int mt = 0; mt < 4; mt++)
#pragma unroll
            for (int half = 0; half < 2; half++) {
                int rl = mt * 16 + (lane >> 2) + half * 8;
                float ss = red[wm * 256 + rl * 4 + wn] +
                           red[wm * 256 + rl * 4 + (wn ^ 1)];
                float inv = 1.0f / fmaxf(sqrtf(ss), 1e-12f);
                if (OUT == 2) inv *= INV_TAU;
                int gr = brow + wm * 64 + rl;
                int bidx = gr >> 11, pos = gr & 2047;
#pragma unroll
                for (int nt = 0; nt < 4; nt++) {
                    int gc = bcol + wn * 32 + nt * 8 + (lane & 3) * 2;
                    int h = gc >> 6, pd = (gc & 63) >> 1;
                    uint32_t hh, ll;
                    split2(acc[mt][nt][half * 2 + 0] * inv,
                           acc[mt][nt][half * 2 + 1] * inv, hh, ll);
                    size_t i0 = ((size_t)(bidx * NHEADS + h) * SEQLEN + pos) * 32 + pd;
                    Hi[i0] = hh;
                    Lo[i0] = ll;
                }
            }
    }
}

// ---------------------------------------------------------------------------
// Flash attention, cp.async 3-stage pipelined tiles (prefetch distance 2).
// Dynamic smem: Khi 3x1152 | Klo 3x1152 | Vs 3x2304 | Ps 2304 = 64512 bytes.
// ---------------------------------------------------------------------------
#define AKH 1152
#define AVS 2304
#define ASM_U32 (3 * AKH + 3 * AKH + 3 * AVS + 2304)
#define ASM_BYTES (ASM_U32 * 4)

__global__ __launch_bounds__(128) void attn_tc(
    const uint32_t* __restrict__ Qh2, const uint32_t* __restrict__ Ql2,
    const uint32_t* __restrict__ Kh2, const uint32_t* __restrict__ Kl2,
    const uint32_t* __restrict__ Vt2,
    uint32_t* __restrict__ Oh, uint32_t* __restrict__ Ol)
{
    extern __shared__ __align__(16) uint32_t adm[];
    uint32_t* KHb = adm;                    // 3 x 1152
    uint32_t* KLb = adm + 3 * AKH;          // 3 x 1152
    uint32_t* VSb = adm + 6 * AKH;          // 3 x 2304
    float*    Ps  = (float*)(adm + 6 * AKH + 3 * AVS);

    const int t    = threadIdx.x;
    const int lane = t & 31, w = t >> 5;
    const int qt   = blockIdx.x;
    const int bh   = blockIdx.y;
    const int b    = bh >> 4, h = bh & 15;
    const size_t hb32 = (size_t)bh * SEQLEN * 32;
    const size_t hb64 = (size_t)bh * SEQLEN * 64;

    const int krow0 = t >> 3, kq4 = t & 7;
    const int vrow0 = t >> 4, vq4 = t & 15;
    const uint32_t* gKh = Kh2 + hb32 + (size_t)krow0 * 32 + kq4 * 4;
    const uint32_t* gKl = Kl2 + hb32 + (size_t)krow0 * 32 + kq4 * 4;
    const uint32_t* gV  = Vt2 + hb64 + (size_t)vrow0 * 64 + vq4 * 4;

    uint32_t sKh[3], sKl[3], sV[3];
#pragma unroll
    for (int s = 0; s < 3; s++) {
        sKh[s] = (uint32_t)__cvta_generic_to_shared(&KHb[s * AKH + krow0 * 36 + kq4 * 4]);
        sKl[s] = (uint32_t)__cvta_generic_to_shared(&KLb[s * AKH + krow0 * 36 + kq4 * 4]);
        sV[s]  = (uint32_t)__cvta_generic_to_shared(&VSb[s * AVS + vrow0 * 72 + vq4 * 4]);
    }

    uint32_t qhi[4][4], qlo[4][4];
    {
        int r = qt * 64 + w * 16 + (lane >> 2);
#pragma unroll
        for (int g = 0; g < 4; g++) {
            int kp0 = g * 8 + (lane & 3);
#pragma unroll
            for (int u = 0; u < 4; u++) {
                int rr = (u & 1) ? r + 8 : r;
                int kp = (u & 2) ? kp0 + 4 : kp0;
                size_t idx = hb32 + (size_t)rr * 32 + kp;
                qhi[g][u] = Qh2[idx];
                qlo[g][u] = Ql2[idx];
            }
        }
    }

    // prologue: tiles 0,1 -> stages 0,1
#pragma unroll
    for (int p = 0; p < 2; p++) {
        size_t koff = (size_t)p * 32 * 32;
        size_t voff = (size_t)p * 32 * 64;
        cpa16(sKh[p], gKh + koff);  cpa16(sKh[p] + 16 * 36 * 4, gKh + koff + 16 * 32);
        cpa16(sKl[p], gKl + koff);  cpa16(sKl[p] + 16 * 36 * 4, gKl + koff + 16 * 32);
#pragma unroll
        for (int i = 0; i < 4; i++)
            cpa16(sV[p] + i * 8 * 72 * 4, gV + voff + (size_t)i * 8 * 64);
        CPA_COMMIT();
    }

    float o[8][4];
#pragma unroll
    for (int n8 = 0; n8 < 8; n8++)
#pragma unroll
        for (int i = 0; i < 4; i++) o[n8][i] = 0.f;
    float m0 = -1e30f, m1 = -1e30f, l0 = 0.f, l1 = 0.f;

    int s = 0;
    for (int kt = 0; kt < SEQLEN / 32; kt++) {
        CPA_WAIT1();
        __syncthreads();
        if (kt < SEQLEN / 32 - 2) {
            int s2 = s + 2; if (s2 >= 3) s2 -= 3;
            size_t koff = (size_t)(kt + 2) * 32 * 32;
            size_t voff = (size_t)(kt + 2) * 32 * 64;
            cpa16(sKh[s2], gKh + koff);  cpa16(sKh[s2] + 16 * 36 * 4, gKh + koff + 16 * 32);
            cpa16(sKl[s2], gKl + koff);  cpa16(sKl[s2] + 16 * 36 * 4, gKl + koff + 16 * 32);
#pragma unroll
            for (int i = 0; i < 4; i++)
                cpa16(sV[s2] + i * 8 * 72 * 4, gV + voff + (size_t)i * 8 * 64);
            CPA_COMMIT();
        } else {
            CPA_COMMIT();
        }

        const uint32_t* Khi = KHb + s * AKH;
        const uint32_t* Klo = KLb + s * AKH;
        const uint32_t* Vs  = VSb + s * AVS;

        float sc[4][4];
#pragma unroll
        for (int nt = 0; nt < 4; nt++)
#pragma unroll
            for (int i = 0; i < 4; i++) sc[nt][i] = 0.f;

#pragma unroll
        for (int g = 0; g < 4; g++) {
            int kp = g * 8 + (lane & 3);
            uint32_t bhf[4][2], blf[4][2];
#pragma unroll
            for (int nt = 0; nt < 4; nt++) {
                int n = nt * 8 + (lane >> 2);
                bhf[nt][0] = Khi[n * 36 + kp];
                bhf[nt][1] = Khi[n * 36 + kp + 4];
                blf[nt][0] = Klo[n * 36 + kp];
                blf[nt][1] = Klo[n * 36 + kp + 4];
            }
#pragma unroll
            for (int nt = 0; nt < 4; nt++) {
                mma16(sc[nt], qhi[g], bhf[nt]);
                mma16(sc[nt], qhi[g], blf[nt]);
                mma16(sc[nt], qlo[g], bhf[nt]);
            }
        }

        float mx0 = -1e30f, mx1 = -1e30f;
#pragma unroll
        for (int nt = 0; nt < 4; nt++) {
            mx0 = fmaxf(mx0, fmaxf(sc[nt][0], sc[nt][1]));
            mx1 = fmaxf(mx1, fmaxf(sc[nt][2], sc[nt][3]));
        }
        mx0 = fmaxf(mx0, __shfl_xor_sync(0xffffffffu, mx0, 1));
        mx0 = fmaxf(mx0, __shfl_xor_sync(0xffffffffu, mx0, 2));
        mx1 = fmaxf(mx1, __shfl_xor_sync(0xffffffffu, mx1, 1));
        mx1 = fmaxf(mx1, __shfl_xor_sync(0xffffffffu, mx1, 2));
        float mn0 = fmaxf(m0, mx0), mn1 = fmaxf(m1, mx1);
        float sc0 = __expf(m0 - mn0), sc1 = __expf(m1 - mn1);
        float sum0 = 0.f, sum1 = 0.f;
#pragma unroll
        for (int nt = 0; nt < 4; nt++) {
            sc[nt][0] = __expf(sc[nt][0] - mn0);
            sc[nt][1] = __expf(sc[nt][1] - mn0);
            sc[nt][2] = __expf(sc[nt][2] - mn1);
            sc[nt][3] = __expf(sc[nt][3] - mn1);
            sum0 += sc[nt][0] + sc[nt][1];
            sum1 += sc[nt][2] + sc[nt][3];
        }
        sum0 += __shfl_xor_sync(0xffffffffu, sum0, 1);
        sum0 += __shfl_xor_sync(0xffffffffu, sum0, 2);
        sum1 += __shfl_xor_sync(0xffffffffu, sum1, 1);
        sum1 += __shfl_xor_sync(0xffffffffu, sum1, 2);
        l0 = l0 * sc0 + sum0;  m0 = mn0;
        l1 = l1 * sc1 + sum1;  m1 = mn1;
#pragma unroll
        for (int n8 = 0; n8 < 8; n8++) {
            o[n8][0] *= sc0; o[n8][1] *= sc0;
            o[n8][2] *= sc1; o[n8][3] *= sc1;
        }

        {
            int r = w * 16 + (lane >> 2);
#pragma unroll
            for (int nt = 0; nt < 4; nt++) {
                int col = nt * 8 + (lane & 3) * 2;
                *(float2*)&Ps[r * 36 + col]       = make_float2(sc[nt][0], sc[nt][1]);
                *(float2*)&Ps[(r + 8) * 36 + col] = make_float2(sc[nt][2], sc[nt][3]);
            }
        }
        __syncwarp();

#pragma unroll
        for (int k8 = 0; k8 < 4; k8++) {
            uint32_t pa[4];
            {
                int r = w * 16 + (lane >> 2);
                int c = (lane & 3) + k8 * 8;
                pa[0] = f2tf32(Ps[r * 36 + c]);
                pa[1] = f2tf32(Ps[(r + 8) * 36 + c]);
                pa[2] = f2tf32(Ps[r * 36 + c + 4]);
                pa[3] = f2tf32(Ps[(r + 8) * 36 + c + 4]);
            }
#pragma unroll
            for (int n8 = 0; n8 < 8; n8++) {
                uint32_t bv[2];
                int kk = (lane & 3) + k8 * 8;
                int n  = (lane >> 2) + n8 * 8;
                bv[0] = Vs[kk * 72 + n];
                bv[1] = Vs[(kk + 4) * 72 + n];
                mma8(o[n8], pa, bv);
            }
        }
        if (++s == 3) s = 0;
    }
    CPA_WAIT0();

    {
        float inv0 = 1.0f / l0, inv1 = 1.0f / l1;
        int rrow = b * SEQLEN + qt * 64 + w * 16 + (lane >> 2);
#pragma unroll
        for (int n8 = 0; n8 < 8; n8++) {
            size_t i0 = (size_t)rrow * 512 + h * 32 + n8 * 4 + (lane & 3);
            size_t i1 = i0 + 8 * 512;
            uint32_t hh, ll;
            split2(o[n8][0] * inv0, o[n8][1] * inv0, hh, ll);
            Oh[i0] = hh; Ol[i0] = ll;
            split2(o[n8][2] * inv1, o[n8][3] * inv1, hh, ll);
            Oh[i1] = hh; Ol[i1] = ll;
        }
    }
}

// ---------------------------------------------------------------------------
extern "C" void kernel_launch(void* const* d_in, const int* in_sizes, int n_in,
                              void* d_out, int out_size)
{
    const float* q  = (const float*)d_in[0];
    const float* k  = (const float*)d_in[1];
    const float* v  = (const float*)d_in[2];
    const float* Wq = (const float*)d_in[3];
    const float* bq = (const float*)d_in[4];
    const float* Wk = (const float*)d_in[5];
    const float* bk = (const float*)d_in[6];
    const float* Wv = (const float*)d_in[7];
    const float* bv = (const float*)d_in[8];
    const float* Wo = (const float*)d_in[9];
    const float* bo = (const float*)d_in[10];
    float* out = (float*)d_out;

    uint32_t *qh, *ql, *kh, *kl, *vh, *vl, *ah, *al;
    uint32_t *wqh, *wql, *wkh, *wkl, *wvh, *wvl, *woh, *wol;
    uint32_t *qh2, *ql2, *kh2, *kl2, *vt2;
    cudaGetSymbolAddress((void**)&qh, g_qh);  cudaGetSymbolAddress((void**)&ql, g_ql);
    cudaGetSymbolAddress((void**)&kh, g_kh);  cudaGetSymbolAddress((void**)&kl, g_kl);
    cudaGetSymbolAddress((void**)&vh, g_vh);  cudaGetSymbolAddress((void**)&vl, g_vl);
    cudaGetSymbolAddress((void**)&ah, g_ah);  cudaGetSymbolAddress((void**)&al, g_al);
    cudaGetSymbolAddress((void**)&wqh, g_wqh); cudaGetSymbolAddress((void**)&wql, g_wql);
    cudaGetSymbolAddress((void**)&wkh, g_wkh); cudaGetSymbolAddress((void**)&wkl, g_wkl);
    cudaGetSymbolAddress((void**)&wvh, g_wvh); cudaGetSymbolAddress((void**)&wvl, g_wvl);
    cudaGetSymbolAddress((void**)&woh, g_woh); cudaGetSymbolAddress((void**)&wol, g_wol);
    cudaGetSymbolAddress((void**)&qh2, g_qh2); cudaGetSymbolAddress((void**)&ql2, g_ql2);
    cudaGetSymbolAddress((void**)&kh2, g_kh2); cudaGetSymbolAddress((void**)&kl2, g_kl2);
    cudaGetSymbolAddress((void**)&vt2, g_vt2);

    cudaFuncSetAttribute(gemm_ps<0>, cudaFuncAttributeMaxDynamicSharedMemorySize, GSM_BYTES);
    cudaFuncSetAttribute(gemm_ps<1>, cudaFuncAttributeMaxDynamicSharedMemorySize, GSM_BYTES);
    cudaFuncSetAttribute(gemm_ps<2>, cudaFuncAttributeMaxDynamicSharedMemorySize, GSM_BYTES);
    cudaFuncSetAttribute(gemm_ps<3>, cudaFuncAttributeMaxDynamicSharedMemorySize, GSM_BYTES);
    cudaFuncSetAttribute(attn_tc,    cudaFuncAttributeMaxDynamicSharedMemorySize, ASM_BYTES);

    const int nAct4 = MROWS * D_MODEL / 4;
    const int nW4   = D_MODEL * D_MODEL / 4;

    splits3<<<nAct4 / 256, 256>>>(q, k, v, qh, ql, kh, kl, vh, vl, nAct4);
    wsplit4<<<dim3(nW4 / 256, 4), 256>>>(Wq, Wk, Wv, Wo,
                                         wqh, wql, wkh, wkl,
                                         wvh, wvl, woh, wol, nW4);

    dim3 ggrid(D_MODEL / 128, MROWS / 128);
    gemm_ps<2><<<ggrid, 256, GSM_BYTES>>>(qh, ql, wqh, wql, bq, qh2, ql2);
    gemm_ps<3><<<ggrid, 256, GSM_BYTES>>>(kh, kl, wkh, wkl, bk, kh2, kl2);
    gemm_ps<1><<<ggrid, 256, GSM_BYTES>>>(vh, vl, wvh, wvl, bv, vt2, nullptr);

    attn_tc<<<dim3(SEQLEN / 64, BATCH * NHEADS), 128, ASM_BYTES>>>(
        qh2, ql2, kh2, kl2, vt2, ah, al);

    gemm_ps<0><<<ggrid, 256, GSM_BYTES>>>(ah, al, woh, wol, bo, out, nullptr);
}

// round 16
// speedup vs baseline: 1.0175x; 1.0175x over previous
#include <cuda_runtime.h>
#include <cstdint>

#define D_MODEL 1024
#define SEQLEN  2048
#define BATCH   4
#define NHEADS  16
#define HDIM    64
#define MROWS   (BATCH * SEQLEN)   /* 8192 */
#define INV_TAU (1.0f / 0.07f)

// ---------------- scratch (__device__ globals; no allocs allowed) ----------
__device__ uint32_t g_qh[MROWS * D_MODEL / 2], g_ql[MROWS * D_MODEL / 2];
__device__ uint32_t g_kh[MROWS * D_MODEL / 2], g_kl[MROWS * D_MODEL / 2];
__device__ uint32_t g_vh[MROWS * D_MODEL / 2], g_vl[MROWS * D_MODEL / 2];
__device__ uint32_t g_ah[MROWS * D_MODEL / 2], g_al[MROWS * D_MODEL / 2];
__device__ uint32_t g_wqh[D_MODEL * D_MODEL / 2], g_wql[D_MODEL * D_MODEL / 2];
__device__ uint32_t g_wkh[D_MODEL * D_MODEL / 2], g_wkl[D_MODEL * D_MODEL / 2];
__device__ uint32_t g_wvh[D_MODEL * D_MODEL / 2], g_wvl[D_MODEL * D_MODEL / 2];
__device__ uint32_t g_woh[D_MODEL * D_MODEL / 2], g_wol[D_MODEL * D_MODEL / 2];
__device__ uint32_t g_qh2[MROWS * D_MODEL / 2], g_ql2[MROWS * D_MODEL / 2];
__device__ uint32_t g_kh2[MROWS * D_MODEL / 2], g_kl2[MROWS * D_MODEL / 2];
__device__ uint32_t g_vt2[MROWS * D_MODEL];

// ---------------- helpers --------------------------------------------------
__device__ __forceinline__ uint32_t f2tf32(float f) {
    uint32_t r; asm("cvt.rna.tf32.f32 %0, %1;" : "=r"(r) : "f"(f)); return r;
}
__device__ __forceinline__ void mma8(float* c, const uint32_t* a, const uint32_t* b) {
    asm volatile("mma.sync.aligned.m16n8k8.row.col.f32.tf32.tf32.f32 "
        "{%0,%1,%2,%3},{%4,%5,%6,%7},{%8,%9},{%0,%1,%2,%3};"
        : "+f"(c[0]), "+f"(c[1]), "+f"(c[2]), "+f"(c[3])
        : "r"(a[0]), "r"(a[1]), "r"(a[2]), "r"(a[3]), "r"(b[0]), "r"(b[1]));
}
__device__ __forceinline__ void mma16(float* c, const uint32_t* a, const uint32_t* b) {
    asm volatile("mma.sync.aligned.m16n8k16.row.col.f32.bf16.bf16.f32 "
        "{%0,%1,%2,%3},{%4,%5,%6,%7},{%8,%9},{%0,%1,%2,%3};"
        : "+f"(c[0]), "+f"(c[1]), "+f"(c[2]), "+f"(c[3])
        : "r"(a[0]), "r"(a[1]), "r"(a[2]), "r"(a[3]), "r"(b[0]), "r"(b[1]));
}
__device__ __forceinline__ uint32_t hipack(float e, float o) {
    return __byte_perm(__float_as_uint(e), __float_as_uint(o), 0x7632);
}
__device__ __forceinline__ uint32_t lopack(float e, float o) {
    uint32_t r; asm("cvt.rn.bf16x2.f32 %0, %1, %2;" : "=r"(r) : "f"(o), "f"(e));
    return r;
}
__device__ __forceinline__ float truncbf(float x) {
    return __uint_as_float(__float_as_uint(x) & 0xffff0000u);
}
__device__ __forceinline__ void split2(float e, float o, uint32_t& h, uint32_t& l) {
    h = hipack(e, o);
    l = lopack(e - truncbf(e), o - truncbf(o));
}
__device__ __forceinline__ void cpa16(uint32_t sdst, const void* gsrc) {
    asm volatile("cp.async.cg.shared.global [%0], [%1], 16;" :: "r"(sdst), "l"(gsrc));
}
#define CPA_COMMIT() asm volatile("cp.async.commit_group;" ::: "memory")
#define CPA_WAIT0()  asm volatile("cp.async.wait_group 0;" ::: "memory")

// ---------------------------------------------------------------------------
__global__ __launch_bounds__(256) void splits3(
    const float* __restrict__ Xq, const float* __restrict__ Xk,
    const float* __restrict__ Xv,
    uint32_t* __restrict__ Hq, uint32_t* __restrict__ Lq,
    uint32_t* __restrict__ Hk, uint32_t* __restrict__ Lk,
    uint32_t* __restrict__ Hv, uint32_t* __restrict__ Lv, int n4)
{
    int i = blockIdx.x * blockDim.x + threadIdx.x;
    if (i >= n4) return;
    float4 a = ((const float4*)Xq)[i];
    float4 b = ((const float4*)Xk)[i];
    float4 c = ((const float4*)Xv)[i];
    uint32_t h0, l0, h1, l1;
    split2(a.x, a.y, h0, l0); split2(a.z, a.w, h1, l1);
    ((uint2*)Hq)[i] = make_uint2(h0, h1); ((uint2*)Lq)[i] = make_uint2(l0, l1);
    split2(b.x, b.y, h0, l0); split2(b.z, b.w, h1, l1);
    ((uint2*)Hk)[i] = make_uint2(h0, h1); ((uint2*)Lk)[i] = make_uint2(l0, l1);
    split2(c.x, c.y, h0, l0); split2(c.z, c.w, h1, l1);
    ((uint2*)Hv)[i] = make_uint2(h0, h1); ((uint2*)Lv)[i] = make_uint2(l0, l1);
}

__global__ __launch_bounds__(256) void wsplit4(
    const float* __restrict__ W0, const float* __restrict__ W1,
    const float* __restrict__ W2, const float* __restrict__ W3,
    uint32_t* __restrict__ H0, uint32_t* __restrict__ L0,
    uint32_t* __restrict__ H1, uint32_t* __restrict__ L1,
    uint32_t* __restrict__ H2, uint32_t* __restrict__ L2,
    uint32_t* __restrict__ H3, uint32_t* __restrict__ L3, int n4)
{
    int i = blockIdx.x * blockDim.x + threadIdx.x;
    if (i >= n4) return;
    int wsel = blockIdx.y;
    const float* X = (wsel == 0) ? W0 : (wsel == 1) ? W1 : (wsel == 2) ? W2 : W3;
    uint32_t* Hi   = (wsel == 0) ? H0 : (wsel == 1) ? H1 : (wsel == 2) ? H2 : H3;
    uint32_t* Lo   = (wsel == 0) ? L0 : (wsel == 1) ? L1 : (wsel == 2) ? L2 : L3;
    float4 v = ((const float4*)X)[i];
    uint32_t h0, l0, h1, l1;
    split2(v.x, v.y, h0, l0);
    split2(v.z, v.w, h1, l1);
    ((uint2*)Hi)[i] = make_uint2(h0, h1);
    ((uint2*)Lo)[i] = make_uint2(l0, l1);
}

// ---------------------------------------------------------------------------
// Split-bf16 GEMM (3-pass), cp.async 2-stage pipeline, PASS-MAJOR mma order
// (16 independent mmas between revisits of each accumulator — no RAW stalls).
// OUT 0: fp32. OUT 1: tf32 per-head. OUT 2/3: fused l2norm(+tau)+split.
// ---------------------------------------------------------------------------
template<int OUT>
__global__ __launch_bounds__(256) void gemm_ps(
    const uint32_t* __restrict__ Ahi, const uint32_t* __restrict__ Alo,
    const uint32_t* __restrict__ Bhi, const uint32_t* __restrict__ Blo,
    const float* __restrict__ bias, void* __restrict__ Cout,
    void* __restrict__ Cout2)
{
    const int N = D_MODEL;
    __shared__ __align__(16) uint32_t AH[2][128 * 12];
    __shared__ __align__(16) uint32_t AL[2][128 * 12];
    __shared__ __align__(16) uint32_t BH[2][128 * 12];
    __shared__ __align__(16) uint32_t BL[2][128 * 12];

    const int t    = threadIdx.x;
    const int lane = t & 31, wid = t >> 5;
    const int wm   = wid >> 2, wn = wid & 3;
    const int brow = blockIdx.y * 128, bcol = blockIdx.x * 128;
    const int lr   = t >> 1;
    const int lkp  = (t & 1) * 4;
    const int sbi  = lr * 12 + lkp;

    const uint32_t* gAh = Ahi + (size_t)(brow + lr) * 512 + lkp;
    const uint32_t* gAl = Alo + (size_t)(brow + lr) * 512 + lkp;
    const uint32_t* gBh = Bhi + (size_t)(bcol + lr) * 512 + lkp;
    const uint32_t* gBl = Blo + (size_t)(bcol + lr) * 512 + lkp;

    uint32_t sAH[2], sAL[2], sBH[2], sBL[2];
#pragma unroll
    for (int s = 0; s < 2; s++) {
        sAH[s] = (uint32_t)__cvta_generic_to_shared(&AH[s][sbi]);
        sAL[s] = (uint32_t)__cvta_generic_to_shared(&AL[s][sbi]);
        sBH[s] = (uint32_t)__cvta_generic_to_shared(&BH[s][sbi]);
        sBL[s] = (uint32_t)__cvta_generic_to_shared(&BL[s][sbi]);
    }

    float acc[4][4][4];
#pragma unroll
    for (int mt = 0; mt < 4; mt++)
#pragma unroll
        for (int nt = 0; nt < 4; nt++)
#pragma unroll
            for (int i = 0; i < 4; i++) acc[mt][nt][i] = 0.f;

    cpa16(sAH[0], gAh); cpa16(sAL[0], gAl);
    cpa16(sBH[0], gBh); cpa16(sBL[0], gBl);
    CPA_COMMIT();

    for (int c = 0; c < 64; c++) {
        const int s = c & 1;
        CPA_WAIT0();
        __syncthreads();
        if (c < 63) {
            const int s2 = s ^ 1;
            cpa16(sAH[s2], gAh + (c + 1) * 8);
            cpa16(sAL[s2], gAl + (c + 1) * 8);
            cpa16(sBH[s2], gBh + (c + 1) * 8);
            cpa16(sBL[s2], gBl + (c + 1) * 8);
            CPA_COMMIT();
        }
        {
            const int kk = lane & 3;
            uint32_t ah[4][4], al[4][4], bh[4][2], bl[4][2];
#pragma unroll
            for (int mt = 0; mt < 4; mt++) {
                int r = wm * 64 + mt * 16 + (lane >> 2);
                ah[mt][0] = AH[s][r * 12 + kk];
                ah[mt][1] = AH[s][(r + 8) * 12 + kk];
                ah[mt][2] = AH[s][r * 12 + kk + 4];
                ah[mt][3] = AH[s][(r + 8) * 12 + kk + 4];
                al[mt][0] = AL[s][r * 12 + kk];
                al[mt][1] = AL[s][(r + 8) * 12 + kk];
                al[mt][2] = AL[s][r * 12 + kk + 4];
                al[mt][3] = AL[s][(r + 8) * 12 + kk + 4];
            }
#pragma unroll
            for (int nt = 0; nt < 4; nt++) {
                int n = wn * 32 + nt * 8 + (lane >> 2);
                bh[nt][0] = BH[s][n * 12 + kk];
                bh[nt][1] = BH[s][n * 12 + kk + 4];
                bl[nt][0] = BL[s][n * 12 + kk];
                bl[nt][1] = BL[s][n * 12 + kk + 4];
            }
            // PASS-MAJOR: hh x16, hl x16, lh x16 (per-acc order unchanged)
#pragma unroll
            for (int mt = 0; mt < 4; mt++)
#pragma unroll
                for (int nt = 0; nt < 4; nt++)
                    mma16(acc[mt][nt], ah[mt], bh[nt]);
#pragma unroll
            for (int mt = 0; mt < 4; mt++)
#pragma unroll
                for (int nt = 0; nt < 4; nt++)
                    mma16(acc[mt][nt], ah[mt], bl[nt]);
#pragma unroll
            for (int mt = 0; mt < 4; mt++)
#pragma unroll
                for (int nt = 0; nt < 4; nt++)
                    mma16(acc[mt][nt], al[mt], bh[nt]);
        }
    }

    // ---- bias ----
#pragma unroll
    for (int nt = 0; nt < 4; nt++) {
        int gc = bcol + wn * 32 + nt * 8 + (lane & 3) * 2;
        float2 bb = *(const float2*)(bias + gc);
#pragma unroll
        for (int mt = 0; mt < 4; mt++) {
            acc[mt][nt][0] += bb.x; acc[mt][nt][1] += bb.y;
            acc[mt][nt][2] += bb.x; acc[mt][nt][3] += bb.y;
        }
    }

    if (OUT == 0 || OUT == 1) {
#pragma unroll
        for (int mt = 0; mt < 4; mt++)
#pragma unroll
            for (int nt = 0; nt < 4; nt++) {
                int gr = brow + wm * 64 + mt * 16 + (lane >> 2);
                int gc = bcol + wn * 32 + nt * 8 + (lane & 3) * 2;
                if (OUT == 0) {
                    float* C = (float*)Cout;
                    *(float2*)(C + (size_t)gr * N + gc) =
                        make_float2(acc[mt][nt][0], acc[mt][nt][1]);
                    *(float2*)(C + (size_t)(gr + 8) * N + gc) =
                        make_float2(acc[mt][nt][2], acc[mt][nt][3]);
                } else {
                    uint32_t* C = (uint32_t*)Cout;
                    int bidx = gr >> 11, pos = gr & 2047;
                    int h = gc >> 6, d = gc & 63;
                    size_t i0 = ((size_t)(bidx * NHEADS + h) * SEQLEN + pos) * 64 + d;
                    *(uint2*)(C + i0)          = make_uint2(f2tf32(acc[mt][nt][0]), f2tf32(acc[mt][nt][1]));
                    *(uint2*)(C + i0 + 8 * 64) = make_uint2(f2tf32(acc[mt][nt][2]), f2tf32(acc[mt][nt][3]));
                }
            }
    } else {
        // ---- fused l2norm + split epilogue ----
        __syncthreads();
        float* red = (float*)AH;
#pragma unroll
        for (int mt = 0; mt < 4; mt++)
#pragma unroll
            for (int half = 0; half < 2; half++) {
                float s2 = 0.f;
#pragma unroll
                for (int nt = 0; nt < 4; nt++) {
                    float v0 = acc[mt][nt][half * 2 + 0];
                    float v1 = acc[mt][nt][half * 2 + 1];
                    s2 += v0 * v0 + v1 * v1;
                }
                s2 += __shfl_xor_sync(0xffffffffu, s2, 1);
                s2 += __shfl_xor_sync(0xffffffffu, s2, 2);
                int rl = mt * 16 + (lane >> 2) + half * 8;
                if ((lane & 3) == 0) red[wm * 256 + rl * 4 + wn] = s2;
            }
        __syncthreads();
        uint32_t* Hi = (uint32_t*)Cout;
        uint32_t* Lo = (uint32_t*)Cout2;
#pragma unroll
        for (int mt = 0; mt < 4; mt++)
#pragma unroll
            for (int half = 0; half < 2; half++) {
                int rl = mt * 16 + (lane >> 2) + half * 8;
                float ss = red[wm * 256 + rl * 4 + wn] +
                           red[wm * 256 + rl * 4 + (wn ^ 1)];
                float inv = 1.0f / fmaxf(sqrtf(ss), 1e-12f);
                if (OUT == 2) inv *= INV_TAU;
                int gr = brow + wm * 64 + rl;
                int bidx = gr >> 11, pos = gr & 2047;
#pragma unroll
                for (int nt = 0; nt < 4; nt++) {
                    int gc = bcol + wn * 32 + nt * 8 + (lane & 3) * 2;
                    int h = gc >> 6, pd = (gc & 63) >> 1;
                    uint32_t hh, ll;
                    split2(acc[mt][nt][half * 2 + 0] * inv,
                           acc[mt][nt][half * 2 + 1] * inv, hh, ll);
                    size_t i0 = ((size_t)(bidx * NHEADS + h) * SEQLEN + pos) * 32 + pd;
                    Hi[i0] = hh;
                    Lo[i0] = ll;
                }
            }
    }
}

// ---------------------------------------------------------------------------
// Flash attention, cp.async 2-stage pipelined tiles, PASS-MAJOR QK mma order.
// ---------------------------------------------------------------------------
__global__ __launch_bounds__(128) void attn_tc(
    const uint32_t* __restrict__ Qh2, const uint32_t* __restrict__ Ql2,
    const uint32_t* __restrict__ Kh2, const uint32_t* __restrict__ Kl2,
    const uint32_t* __restrict__ Vt2,
    uint32_t* __restrict__ Oh, uint32_t* __restrict__ Ol)
{
    __shared__ __align__(16) uint32_t Khi[2][32 * 36];
    __shared__ __align__(16) uint32_t Klo[2][32 * 36];
    __shared__ __align__(16) uint32_t Vs[2][32 * 72];
    __shared__ float Ps[64 * 36];

    const int t    = threadIdx.x;
    const int lane = t & 31, w = t >> 5;
    const int qt   = blockIdx.x;
    const int bh   = blockIdx.y;
    const int b    = bh >> 4, h = bh & 15;
    const size_t hb32 = (size_t)bh * SEQLEN * 32;
    const size_t hb64 = (size_t)bh * SEQLEN * 64;

    const int krow0 = t >> 3, kq4 = t & 7;
    const int vrow0 = t >> 4, vq4 = t & 15;
    const uint32_t* gKh = Kh2 + hb32 + (size_t)krow0 * 32 + kq4 * 4;
    const uint32_t* gKl = Kl2 + hb32 + (size_t)krow0 * 32 + kq4 * 4;
    const uint32_t* gV  = Vt2 + hb64 + (size_t)vrow0 * 64 + vq4 * 4;

    uint32_t sKh[2], sKl[2], sV[2];
#pragma unroll
    for (int s = 0; s < 2; s++) {
        sKh[s] = (uint32_t)__cvta_generic_to_shared(&Khi[s][krow0 * 36 + kq4 * 4]);
        sKl[s] = (uint32_t)__cvta_generic_to_shared(&Klo[s][krow0 * 36 + kq4 * 4]);
        sV[s]  = (uint32_t)__cvta_generic_to_shared(&Vs[s][vrow0 * 72 + vq4 * 4]);
    }

    uint32_t qhi[4][4], qlo[4][4];
    {
        int r = qt * 64 + w * 16 + (lane >> 2);
#pragma unroll
        for (int g = 0; g < 4; g++) {
            int kp0 = g * 8 + (lane & 3);
#pragma unroll
            for (int u = 0; u < 4; u++) {
                int rr = (u & 1) ? r + 8 : r;
                int kp = (u & 2) ? kp0 + 4 : kp0;
                size_t idx = hb32 + (size_t)rr * 32 + kp;
                qhi[g][u] = Qh2[idx];
                qlo[g][u] = Ql2[idx];
            }
        }
    }

    {
        cpa16(sKh[0], gKh);  cpa16(sKh[0] + 16 * 36 * 4, gKh + 16 * 32);
        cpa16(sKl[0], gKl);  cpa16(sKl[0] + 16 * 36 * 4, gKl + 16 * 32);
#pragma unroll
        for (int i = 0; i < 4; i++)
            cpa16(sV[0] + i * 8 * 72 * 4, gV + (size_t)i * 8 * 64);
        CPA_COMMIT();
    }

    float o[8][4];
#pragma unroll
    for (int n8 = 0; n8 < 8; n8++)
#pragma unroll
        for (int i = 0; i < 4; i++) o[n8][i] = 0.f;
    float m0 = -1e30f, m1 = -1e30f, l0 = 0.f, l1 = 0.f;

    for (int kt = 0; kt < SEQLEN / 32; kt++) {
        const int s = kt & 1;
        CPA_WAIT0();
        __syncthreads();
        if (kt < SEQLEN / 32 - 1) {
            const int s2 = s ^ 1;
            size_t koff = (size_t)(kt + 1) * 32 * 32;
            size_t voff = (size_t)(kt + 1) * 32 * 64;
            cpa16(sKh[s2], gKh + koff);  cpa16(sKh[s2] + 16 * 36 * 4, gKh + koff + 16 * 32);
            cpa16(sKl[s2], gKl + koff);  cpa16(sKl[s2] + 16 * 36 * 4, gKl + koff + 16 * 32);
#pragma unroll
            for (int i = 0; i < 4; i++)
                cpa16(sV[s2] + i * 8 * 72 * 4, gV + voff + (size_t)i * 8 * 64);
            CPA_COMMIT();
        }

        float sc[4][4];
#pragma unroll
        for (int nt = 0; nt < 4; nt++)
#pragma unroll
            for (int i = 0; i < 4; i++) sc[nt][i] = 0.f;

#pragma unroll
        for (int g = 0; g < 4; g++) {
            int kp = g * 8 + (lane & 3);
            uint32_t bhf[4][2], blf[4][2];
#pragma unroll
            for (int nt = 0; nt < 4; nt++) {
                int n = nt * 8 + (lane >> 2);
                bhf[nt][0] = Khi[s][n * 36 + kp];
                bhf[nt][1] = Khi[s][n * 36 + kp + 4];
                blf[nt][0] = Klo[s][n * 36 + kp];
                blf[nt][1] = Klo[s][n * 36 + kp + 4];
            }
            // PASS-MAJOR: hh x4, hl x4, lh x4
#pragma unroll
            for (int nt = 0; nt < 4; nt++) mma16(sc[nt], qhi[g], bhf[nt]);
#pragma unroll
            for (int nt = 0; nt < 4; nt++) mma16(sc[nt], qhi[g], blf[nt]);
#pragma unroll
            for (int nt = 0; nt < 4; nt++) mma16(sc[nt], qlo[g], bhf[nt]);
        }

        float mx0 = -1e30f, mx1 = -1e30f;
#pragma unroll
        for (int nt = 0; nt < 4; nt++) {
            mx0 = fmaxf(mx0, fmaxf(sc[nt][0], sc[nt][1]));
            mx1 = fmaxf(mx1, fmaxf(sc[nt][2], sc[nt][3]));
        }
        mx0 = fmaxf(mx0, __shfl_xor_sync(0xffffffffu, mx0, 1));
        mx0 = fmaxf(mx0, __shfl_xor_sync(0xffffffffu, mx0, 2));
        mx1 = fmaxf(mx1, __shfl_xor_sync(0xffffffffu, mx1, 1));
        mx1 = fmaxf(mx1, __shfl_xor_sync(0xffffffffu, mx1, 2));
        float mn0 = fmaxf(m0, mx0), mn1 = fmaxf(m1, mx1);
        float sc0 = __expf(m0 - mn0), sc1 = __expf(m1 - mn1);
        float sum0 = 0.f, sum1 = 0.f;
#pragma unroll
        for (int nt = 0; nt < 4; nt++) {
            sc[nt][0] = __expf(sc[nt][0] - mn0);
            sc[nt][1] = __expf(sc[nt][1] - mn0);
            sc[nt][2] = __expf(sc[nt][2] - mn1);
            sc[nt][3] = __expf(sc[nt][3] - mn1);
            sum0 += sc[nt][0] + sc[nt][1];
            sum1 += sc[nt][2] + sc[nt][3];
        }
        sum0 += __shfl_xor_sync(0xffffffffu, sum0, 1);
        sum0 += __shfl_xor_sync(0xffffffffu, sum0, 2);
        sum1 += __shfl_xor_sync(0xffffffffu, sum1, 1);
        sum1 += __shfl_xor_sync(0xffffffffu, sum1, 2);
        l0 = l0 * sc0 + sum0;  m0 = mn0;
        l1 = l1 * sc1 + sum1;  m1 = mn1;
#pragma unroll
        for (int n8 = 0; n8 < 8; n8++) {
            o[n8][0] *= sc0; o[n8][1] *= sc0;
            o[n8][2] *= sc1; o[n8][3] *= sc1;
        }

        {
            int r = w * 16 + (lane >> 2);
#pragma unroll
            for (int nt = 0; nt < 4; nt++) {
                int col = nt * 8 + (lane & 3) * 2;
                *(float2*)&Ps[r * 36 + col]       = make_float2(sc[nt][0], sc[nt][1]);
                *(float2*)&Ps[(r + 8) * 36 + col] = make_float2(sc[nt][2], sc[nt][3]);
            }
        }
        __syncwarp();

#pragma unroll
        for (int k8 = 0; k8 < 4; k8++) {
            uint32_t pa[4];
            {
                int r = w * 16 + (lane >> 2);
                int c = (lane & 3) + k8 * 8;
                pa[0] = f2tf32(Ps[r * 36 + c]);
                pa[1] = f2tf32(Ps[(r + 8) * 36 + c]);
                pa[2] = f2tf32(Ps[r * 36 + c + 4]);
                pa[3] = f2tf32(Ps[(r + 8) * 36 + c + 4]);
            }
#pragma unroll
            for (int n8 = 0; n8 < 8; n8++) {
                uint32_t bv[2];
                int kk = (lane & 3) + k8 * 8;
                int n  = (lane >> 2) + n8 * 8;
                bv[0] = Vs[s][kk * 72 + n];
                bv[1] = Vs[s][(kk + 4) * 72 + n];
                mma8(o[n8], pa, bv);
            }
        }
    }

    {
        float inv0 = 1.0f / l0, inv1 = 1.0f / l1;
        int rrow = b * SEQLEN + qt * 64 + w * 16 + (lane >> 2);
#pragma unroll
        for (int n8 = 0; n8 < 8; n8++) {
            size_t i0 = (size_t)rrow * 512 + h * 32 + n8 * 4 + (lane & 3);
            size_t i1 = i0 + 8 * 512;
            uint32_t hh, ll;
            split2(o[n8][0] * inv0, o[n8][1] * inv0, hh, ll);
            Oh[i0] = hh; Ol[i0] = ll;
            split2(o[n8][2] * inv1, o[n8][3] * inv1, hh, ll);
            Oh[i1] = hh; Ol[i1] = ll;
        }
    }
}

// ---------------------------------------------------------------------------
extern "C" void kernel_launch(void* const* d_in, const int* in_sizes, int n_in,
                              void* d_out, int out_size)
{
    const float* q  = (const float*)d_in[0];
    const float* k  = (const float*)d_in[1];
    const float* v  = (const float*)d_in[2];
    const float* Wq = (const float*)d_in[3];
    const float* bq = (const float*)d_in[4];
    const float* Wk = (const float*)d_in[5];
    const float* bk = (const float*)d_in[6];
    const float* Wv = (const float*)d_in[7];
    const float* bv = (const float*)d_in[8];
    const float* Wo = (const float*)d_in[9];
    const float* bo = (const float*)d_in[10];
    float* out = (float*)d_out;

    uint32_t *qh, *ql, *kh, *kl, *vh, *vl, *ah, *al;
    uint32_t *wqh, *wql, *wkh, *wkl, *wvh, *wvl, *woh, *wol;
    uint32_t *qh2, *ql2, *kh2, *kl2, *vt2;
    cudaGetSymbolAddress((void**)&qh, g_qh);  cudaGetSymbolAddress((void**)&ql, g_ql);
    cudaGetSymbolAddress((void**)&kh, g_kh);  cudaGetSymbolAddress((void**)&kl, g_kl);
    cudaGetSymbolAddress((void**)&vh, g_vh);  cudaGetSymbolAddress((void**)&vl, g_vl);
    cudaGetSymbolAddress((void**)&ah, g_ah);  cudaGetSymbolAddress((void**)&al, g_al);
    cudaGetSymbolAddress((void**)&wqh, g_wqh); cudaGetSymbolAddress((void**)&wql, g_wql);
    cudaGetSymbolAddress((void**)&wkh, g_wkh); cudaGetSymbolAddress((void**)&wkl, g_wkl);
    cudaGetSymbolAddress((void**)&wvh, g_wvh); cudaGetSymbolAddress((void**)&wvl, g_wvl);
    cudaGetSymbolAddress((void**)&woh, g_woh); cudaGetSymbolAddress((void**)&wol, g_wol);
    cudaGetSymbolAddress((void**)&qh2, g_qh2); cudaGetSymbolAddress((void**)&ql2, g_ql2);
    cudaGetSymbolAddress((void**)&kh2, g_kh2); cudaGetSymbolAddress((void**)&kl2, g_kl2);
    cudaGetSymbolAddress((void**)&vt2, g_vt2);

    const int nAct4 = MROWS * D_MODEL / 4;
    const int nW4   = D_MODEL * D_MODEL / 4;

    splits3<<<nAct4 / 256, 256>>>(q, k, v, qh, ql, kh, kl, vh, vl, nAct4);
    wsplit4<<<dim3(nW4 / 256, 4), 256>>>(Wq, Wk, Wv, Wo,
                                         wqh, wql, wkh, wkl,
                                         wvh, wvl, woh, wol, nW4);

    dim3 ggrid(D_MODEL / 128, MROWS / 128);
    gemm_ps<2><<<ggrid, 256>>>(qh, ql, wqh, wql, bq, qh2, ql2);
    gemm_ps<3><<<ggrid, 256>>>(kh, kl, wkh, wkl, bk, kh2, kl2);
    gemm_ps<1><<<ggrid, 256>>>(vh, vl, wvh, wvl, bv, vt2, nullptr);

    attn_tc<<<dim3(SEQLEN / 64, BATCH * NHEADS), 128>>>(qh2, ql2, kh2, kl2, vt2, ah, al);

    gemm_ps<0><<<ggrid, 256>>>(ah, al, woh, wol, bo, out, nullptr);
}